// round 11
// baseline (speedup 1.0000x reference)
#include <cuda_runtime.h>
#include <cuda_bf16.h>
#include <math.h>
#include <stdint.h>

#define Nn 10000
#define Ee 160000
#define EPE 170000      // E + N self loops
#define Dd 128
#define HC 512
#define KT2 32          // gemm2 k-tile
#define ASTRIDE 136     // padded bf16 row stride (272B = 17 x 16B -> conflict-free ldmatrix)

typedef unsigned long long u64;

// ---------------- packed f32x2 helpers (sm_103a) ----------------
__device__ __forceinline__ u64 pk2(float lo, float hi) {
    u64 r; asm("mov.b64 %0, {%1, %2};" : "=l"(r) : "f"(lo), "f"(hi)); return r;
}
__device__ __forceinline__ void fma2(u64& d, u64 a, u64 b) {
    asm("fma.rn.f32x2 %0, %1, %2, %0;" : "+l"(d) : "l"(a), "l"(b));
}
__device__ __forceinline__ void upk2(u64 v, float& lo, float& hi) {
    asm("mov.b64 {%0, %1}, %2;" : "=f"(lo), "=f"(hi) : "l"(v));
}

// ---------------- cp.async helpers ----------------
__device__ __forceinline__ uint32_t saddr(const void* p) {
    return (uint32_t)__cvta_generic_to_shared(p);
}
__device__ __forceinline__ void cp16(uint32_t dst, const void* src) {
    asm volatile("cp.async.ca.shared.global [%0], [%1], 16;\n" :: "r"(dst), "l"(src));
}
__device__ __forceinline__ void cp_commit() { asm volatile("cp.async.commit_group;\n"); }
__device__ __forceinline__ void cp_wait0()  { asm volatile("cp.async.wait_group 0;\n"); }

// ---------------- mma.sync helpers ----------------
__device__ __forceinline__ void ldsm4(uint32_t* r, uint32_t addr) {
    asm volatile("ldmatrix.sync.aligned.m8n8.x4.shared.b16 {%0,%1,%2,%3}, [%4];"
        : "=r"(r[0]), "=r"(r[1]), "=r"(r[2]), "=r"(r[3]) : "r"(addr));
}
__device__ __forceinline__ void mma16816(float* c, const uint32_t* a, uint32_t b0, uint32_t b1) {
    asm volatile(
        "mma.sync.aligned.m16n8k16.row.col.f32.bf16.bf16.f32 "
        "{%0,%1,%2,%3}, {%4,%5,%6,%7}, {%8,%9}, {%0,%1,%2,%3};"
        : "+f"(c[0]), "+f"(c[1]), "+f"(c[2]), "+f"(c[3])
        : "r"(a[0]), "r"(a[1]), "r"(a[2]), "r"(a[3]), "r"(b0), "r"(b1));
}

// ---------------- device scratch ----------------
__device__ float g_xl[Nn * HC];
__device__ float g_xr[Nn * HC];
__device__ float g_agg[Nn * HC];
__device__ __nv_bfloat16 g_xlb[Nn * HC];        // bf16 copy of xl for aggregation
__device__ int   g_deg[Nn];
__device__ int   g_off[Nn + 1];
__device__ int   g_cur[Nn];
__device__ int   g_esrc[EPE];
__device__ float g_eav[EPE];
__device__ float g_easum;
__device__ __nv_bfloat16 g_xhi[Nn * Dd];
__device__ __nv_bfloat16 g_xlo[Nn * Dd];
__device__ __nv_bfloat16 g_wthi[2 * HC * Dd];   // [mat][n][k] = W[k][n]
__device__ __nv_bfloat16 g_wtlo[2 * HC * Dd];

// ---------------- init ----------------
__global__ void k_init() {
    int i = blockIdx.x * blockDim.x + threadIdx.x;
    if (i < Nn) { g_deg[i] = 0; g_cur[i] = 0; }
    if (i == 0) g_easum = 0.f;
}

// ---------------- convert x -> bf16 hi/lo ----------------
__global__ void k_cvt_x(const float* __restrict__ x) {
    int i = blockIdx.x * 256 + threadIdx.x;
    if (i >= Nn * Dd / 2) return;
    float2 v = ((const float2*)x)[i];
    __nv_bfloat16 h0 = __float2bfloat16(v.x), h1 = __float2bfloat16(v.y);
    __nv_bfloat16 l0 = __float2bfloat16(v.x - __bfloat162float(h0));
    __nv_bfloat16 l1 = __float2bfloat16(v.y - __bfloat162float(h1));
    ((__nv_bfloat162*)g_xhi)[i] = __halves2bfloat162(h0, h1);
    ((__nv_bfloat162*)g_xlo)[i] = __halves2bfloat162(l0, l1);
}

// ---------------- transpose+convert W -> wt[n][k] bf16 hi/lo --------------
__global__ void k_cvt_w(const float* __restrict__ Wl, const float* __restrict__ Wr) {
    __shared__ float t[32][33];
    int m = blockIdx.z;
    const float* W = m ? Wr : Wl;
    int nb = blockIdx.x * 32, kb = blockIdx.y * 32;
    int tx = threadIdx.x, ty = threadIdx.y;
#pragma unroll
    for (int j = 0; j < 4; j++)
        t[ty + 8 * j][tx] = W[(kb + ty + 8 * j) * HC + nb + tx];
    __syncthreads();
#pragma unroll
    for (int j = 0; j < 4; j++) {
        float v = t[tx][ty + 8 * j];
        __nv_bfloat16 h = __float2bfloat16(v);
        __nv_bfloat16 l = __float2bfloat16(v - __bfloat162float(h));
        int o = m * HC * Dd + (nb + ty + 8 * j) * Dd + kb + tx;
        g_wthi[o] = h;
        g_wtlo[o] = l;
    }
}

// ---------------- GEMM1 via mma.sync bf16 (split hh+hl+lh) -----------------
// CTA 128x128, 16 warps (4x4), warp tile 32x32 -> 32 acc regs, 4 warps/SMSP.
#define SMEM_G1 (4 * 128 * ASTRIDE * 2)   // 139264 B

__global__ __launch_bounds__(512) void k_gemm1_mma(const float* __restrict__ bl,
                                                   const float* __restrict__ br) {
    extern __shared__ __nv_bfloat16 smb[];
    __nv_bfloat16* Ah = smb;
    __nv_bfloat16* Al = Ah + 128 * ASTRIDE;
    __nv_bfloat16* Bh = Al + 128 * ASTRIDE;
    __nv_bfloat16* Bl = Bh + 128 * ASTRIDE;

    int tid = threadIdx.x, wid = tid >> 5, lane = tid & 31;
    int cb = blockIdx.y;
    int mat = cb >> 2, colbase = (cb & 3) * 128;
    const float* bias = mat ? br : bl;
    float* out = mat ? g_xr : g_xl;
    int row0 = blockIdx.x * 128;

    const __nv_bfloat16* gbh = g_wthi + (size_t)mat * HC * Dd + (size_t)colbase * Dd;
    const __nv_bfloat16* gbl = g_wtlo + (size_t)mat * HC * Dd + (size_t)colbase * Dd;

    // ---- fill 4 smem arrays (row-major, padded stride) ----
#pragma unroll
    for (int i = 0; i < 4; i++) {
        int idx = tid + i * 512;           // 0..2047
        int row = idx >> 4, ch = idx & 15;
        int grow = row0 + row;
        uint4 vh = make_uint4(0, 0, 0, 0), vl = make_uint4(0, 0, 0, 0);
        if (grow < Nn) {
            vh = *(const uint4*)(g_xhi + (size_t)grow * Dd + ch * 8);
            vl = *(const uint4*)(g_xlo + (size_t)grow * Dd + ch * 8);
        }
        *(uint4*)(Ah + row * ASTRIDE + ch * 8) = vh;
        *(uint4*)(Al + row * ASTRIDE + ch * 8) = vl;
        *(uint4*)(Bh + row * ASTRIDE + ch * 8) = *(const uint4*)(gbh + row * Dd + ch * 8);
        *(uint4*)(Bl + row * ASTRIDE + ch * 8) = *(const uint4*)(gbl + row * Dd + ch * 8);
    }
    __syncthreads();

    float acc[2][4][4];
#pragma unroll
    for (int mt = 0; mt < 2; mt++)
#pragma unroll
        for (int nt = 0; nt < 4; nt++)
#pragma unroll
            for (int j = 0; j < 4; j++) acc[mt][nt][j] = 0.f;

    int warpM = wid & 3, warpN = wid >> 2;
    int mbase = warpM * 32, nbase = warpN * 32;
    int t8 = lane >> 3, r8 = lane & 7;
    int aRow = (t8 & 1) * 8 + r8, aK = (t8 >> 1) * 8;
    int bN = (t8 >> 1) * 8 + r8, bK = (t8 & 1) * 8;

#pragma unroll
    for (int term = 0; term < 3; term++) {
        const __nv_bfloat16* Asm = (term == 2) ? Al : Ah;
        const __nv_bfloat16* Bsm = (term == 1) ? Bl : Bh;
#pragma unroll
        for (int ks = 0; ks < 8; ks++) {
            uint32_t a[2][4], b[2][4];
#pragma unroll
            for (int mt = 0; mt < 2; mt++)
                ldsm4(a[mt], saddr(Asm + (mbase + mt * 16 + aRow) * ASTRIDE + ks * 16 + aK));
#pragma unroll
            for (int g = 0; g < 2; g++)
                ldsm4(b[g], saddr(Bsm + (nbase + g * 16 + bN) * ASTRIDE + ks * 16 + bK));
#pragma unroll
            for (int mt = 0; mt < 2; mt++)
#pragma unroll
                for (int nt = 0; nt < 4; nt++)
                    mma16816(acc[mt][nt], a[mt],
                             b[nt >> 1][(nt & 1) * 2], b[nt >> 1][(nt & 1) * 2 + 1]);
        }
    }

    // ---- epilogue ----
    int rA = lane >> 2, cA = 2 * (lane & 3);
#pragma unroll
    for (int nt = 0; nt < 4; nt++) {
        int col = colbase + nbase + nt * 8 + cA;
        float2 bv = *(const float2*)(bias + col);
#pragma unroll
        for (int mt = 0; mt < 2; mt++) {
            int row = row0 + mbase + mt * 16 + rA;
            if (row < Nn) {
                float2 o = make_float2(acc[mt][nt][0] + bv.x, acc[mt][nt][1] + bv.y);
                *(float2*)(out + (size_t)row * HC + col) = o;
                if (mat == 0)
                    *(__nv_bfloat162*)(g_xlb + (size_t)row * HC + col) =
                        __floats2bfloat162_rn(o.x, o.y);
            }
            if (row + 8 < Nn) {
                float2 o = make_float2(acc[mt][nt][2] + bv.x, acc[mt][nt][3] + bv.y);
                *(float2*)(out + (size_t)(row + 8) * HC + col) = o;
                if (mat == 0)
                    *(__nv_bfloat162*)(g_xlb + (size_t)(row + 8) * HC + col) =
                        __floats2bfloat162_rn(o.x, o.y);
            }
        }
    }
}

// ---------------- degree histogram + edge_attr sum (fused) ----------------
__global__ void k_degree(const int* __restrict__ ei, const float* __restrict__ ea) {
    __shared__ float sh[8];
    int e = blockIdx.x * blockDim.x + threadIdx.x;
    float v = 0.f;
    if (e < EPE) {
        int dst = (e < Ee) ? ei[Ee + e] : (e - Ee);
        atomicAdd(&g_deg[dst], 1);
        if (e < Ee) v = ea[e];
    }
#pragma unroll
    for (int o = 16; o; o >>= 1) v += __shfl_xor_sync(0xffffffffu, v, o);
    if ((threadIdx.x & 31) == 0) sh[threadIdx.x >> 5] = v;
    __syncthreads();
    if (threadIdx.x == 0) {
        float s = 0.f;
#pragma unroll
        for (int w = 0; w < 8; w++) s += sh[w];
        atomicAdd(&g_easum, s);
    }
}

// ---------------- exclusive scan over N (single block) ----------------
__global__ void k_scan() {
    __shared__ int sb[1024];
    int t = threadIdx.x;
    const int CH = 10;
    int lo = t * CH;
    int s = 0;
    for (int i = 0; i < CH; i++) { int idx = lo + i; if (idx < Nn) s += g_deg[idx]; }
    sb[t] = s;
    __syncthreads();
    for (int o = 1; o < 1024; o <<= 1) {
        int v = (t >= o) ? sb[t - o] : 0;
        __syncthreads();
        sb[t] += v;
        __syncthreads();
    }
    int run = sb[t] - s;
    for (int i = 0; i < CH; i++) {
        int idx = lo + i;
        if (idx < Nn) { g_off[idx] = run; run += g_deg[idx]; }
    }
    if (t == 1023) g_off[Nn] = sb[1023];
}

// ---------------- scatter edges into CSR by dst ----------------
__global__ void k_scatter(const int* __restrict__ ei, const float* __restrict__ ea) {
    int e = blockIdx.x * blockDim.x + threadIdx.x;
    if (e >= EPE) return;
    int src, dst; float a;
    if (e < Ee) { src = ei[e]; dst = ei[Ee + e]; a = ea[e]; }
    else        { src = e - Ee; dst = src; a = g_easum * (1.0f / Ee); }
    int pos = atomicAdd(&g_cur[dst], 1);
    int idx = g_off[dst] + pos;
    g_esrc[idx] = src;
    g_eav[idx]  = a;
}

// ---------------- warp-per-node aggregation, bf16 values ------------------
__global__ __launch_bounds__(256) void k_aggregate(const float* __restrict__ We,
        const float* __restrict__ att, const float* __restrict__ bias_out) {
    int gw = (blockIdx.x * 256 + threadIdx.x) >> 5;
    if (gw >= Nn) return;
    int lane = threadIdx.x & 31;
    int co = lane * 4;

    float xr[16], we[16], at[16];
#pragma unroll
    for (int q = 0; q < 4; q++) {
        *(float4*)&xr[q*4] = *(const float4*)(g_xr + gw * HC + q * 128 + co);
        *(float4*)&we[q*4] = *(const float4*)(We + q * 128 + co);
        *(float4*)&at[q*4] = *(const float4*)(att + q * 128 + co);
    }

    float ssum[4] = {0.f, 0.f, 0.f, 0.f};
    float acc[16];
#pragma unroll
    for (int k = 0; k < 16; k++) acc[k] = 0.f;

    int e0 = g_off[gw], e1 = g_off[gw + 1];

    uint2 bufA[4], bufB[4];
    auto ldxv = [&](uint2* d, int s) {
#pragma unroll
        for (int q = 0; q < 4; q++)
            d[q] = *(const uint2*)(g_xlb + (size_t)s * HC + q * 128 + co);
    };
    auto process = [&](const uint2* d, float a) {
        float xv[16];
#pragma unroll
        for (int q = 0; q < 4; q++) {           // bf16 -> f32 (exact expand)
            xv[q*4+0] = __uint_as_float(d[q].x << 16);
            xv[q*4+1] = __uint_as_float(d[q].x & 0xffff0000u);
            xv[q*4+2] = __uint_as_float(d[q].y << 16);
            xv[q*4+3] = __uint_as_float(d[q].y & 0xffff0000u);
        }
        float p[4];
#pragma unroll
        for (int q = 0; q < 4; q++) {
            float pq = 0.f;
#pragma unroll
            for (int j = 0; j < 4; j++) {
                float z = xv[q*4+j] + fmaf(a, we[q*4+j], xr[q*4+j]);
                z = fmaxf(z, 0.2f * z);
                pq = fmaf(z, at[q*4+j], pq);
            }
            p[q] = pq;
        }
#pragma unroll
        for (int o = 16; o; o >>= 1) {
            p[0] += __shfl_xor_sync(0xffffffffu, p[0], o);
            p[1] += __shfl_xor_sync(0xffffffffu, p[1], o);
            p[2] += __shfl_xor_sync(0xffffffffu, p[2], o);
            p[3] += __shfl_xor_sync(0xffffffffu, p[3], o);
        }
        float w0 = __expf(p[0]), w1 = __expf(p[1]);
        float w2 = __expf(p[2]), w3 = __expf(p[3]);
        ssum[0] += w0; ssum[1] += w1; ssum[2] += w2; ssum[3] += w3;
#pragma unroll
        for (int j = 0; j < 4; j++) {
            acc[j]    = fmaf(w0, xv[j],    acc[j]);
            acc[4+j]  = fmaf(w1, xv[4+j],  acc[4+j]);
            acc[8+j]  = fmaf(w2, xv[8+j],  acc[8+j]);
            acc[12+j] = fmaf(w3, xv[12+j], acc[12+j]);
        }
    };

    if (e0 < e1) {
        ldxv(bufA, g_esrc[e0]);
        int e = e0;
        for (; e + 2 <= e1; e += 2) {
            ldxv(bufB, g_esrc[e + 1]);
            process(bufA, g_eav[e]);
            if (e + 2 < e1) ldxv(bufA, g_esrc[e + 2]);
            process(bufB, g_eav[e + 1]);
        }
        if (e < e1) process(bufA, g_eav[e]);
    }

    float invq[4];
#pragma unroll
    for (int q = 0; q < 4; q++) invq[q] = 1.f / (ssum[q] + 1e-16f);
#pragma unroll
    for (int q = 0; q < 4; q++) {
        float4 bo = *(const float4*)(bias_out + q * 128 + co);
        float4 o4;
        o4.x = fmaf(acc[q*4+0], invq[q], bo.x);
        o4.y = fmaf(acc[q*4+1], invq[q], bo.y);
        o4.z = fmaf(acc[q*4+2], invq[q], bo.z);
        o4.w = fmaf(acc[q*4+3], invq[q], bo.w);
        *(float4*)(g_agg + gw * HC + q * 128 + co) = o4;
    }
}

// ---------------- GEMM2 + residual + GELU + LayerNorm fused ----------------
__global__ __launch_bounds__(256, 3) void k_gemm2(const float* __restrict__ x,
        const float* __restrict__ Wp, const float* __restrict__ bp,
        const float* __restrict__ gamma, const float* __restrict__ beta,
        float* __restrict__ out) {
    __shared__ float As[2][KT2][64];
    __shared__ float Bs[2][KT2][128];
    int row0 = blockIdx.x * 64;
    int tid = threadIdx.x;
    int ty = tid >> 4, tx = tid & 15;

    u64 acc[2][8];
#pragma unroll
    for (int r = 0; r < 2; r++)
#pragma unroll
        for (int c = 0; c < 8; c++) acc[r][c] = 0ull;

    int rA0 = tid & 63,         kqA0 = tid >> 6;
    int rA1 = (tid + 256) & 63, kqA1 = (tid + 256) >> 6;
    float4 pf0, pf1;

    auto ldA = [&](int kt) {
        int g0 = row0 + rA0, g1 = row0 + rA1;
        pf0 = (g0 < Nn) ? *(const float4*)(g_agg + g0 * HC + kt + kqA0 * 4) : make_float4(0.f,0.f,0.f,0.f);
        pf1 = (g1 < Nn) ? *(const float4*)(g_agg + g1 * HC + kt + kqA1 * 4) : make_float4(0.f,0.f,0.f,0.f);
    };
    auto stA = [&](int b) {
        As[b][kqA0*4+0][rA0] = pf0.x; As[b][kqA0*4+1][rA0] = pf0.y;
        As[b][kqA0*4+2][rA0] = pf0.z; As[b][kqA0*4+3][rA0] = pf0.w;
        As[b][kqA1*4+0][rA1] = pf1.x; As[b][kqA1*4+1][rA1] = pf1.y;
        As[b][kqA1*4+2][rA1] = pf1.z; As[b][kqA1*4+3][rA1] = pf1.w;
    };
    auto cpB = [&](int kt, int b) {
#pragma unroll
        for (int i = 0; i < 4; i++) {
            int idx = tid + i * 256;
            int k = idx >> 5, c4 = (idx & 31) * 4;
            cp16(saddr(&Bs[b][k][c4]), Wp + (kt + k) * Dd + c4);
        }
    };

    const int NT = HC / KT2;
    ldA(0);
    cpB(0, 0); cp_commit();
    stA(0);
    ldA(KT2);
    cp_wait0();
    __syncthreads();

#pragma unroll 1
    for (int kti = 0; kti < NT; kti++) {
        int b = kti & 1;
        if (kti < NT - 1) {
            cpB((kti + 1) * KT2, b ^ 1); cp_commit();
            stA(b ^ 1);
            if (kti < NT - 2) ldA((kti + 2) * KT2);
        }
#pragma unroll
        for (int k = 0; k < KT2; k++) {
            ulonglong2 A01 = *(ulonglong2*)&As[b][k][ty * 4];
            float4 b0 = *(float4*)&Bs[b][k][tx * 4];
            float4 b1 = *(float4*)&Bs[b][k][tx * 4 + 64];
            u64 B0 = pk2(b0.x, b0.x), B1 = pk2(b0.y, b0.y);
            u64 B2 = pk2(b0.z, b0.z), B3 = pk2(b0.w, b0.w);
            u64 B4 = pk2(b1.x, b1.x), B5 = pk2(b1.y, b1.y);
            u64 B6 = pk2(b1.z, b1.z), B7 = pk2(b1.w, b1.w);
            fma2(acc[0][0], A01.x, B0); fma2(acc[0][1], A01.x, B1);
            fma2(acc[0][2], A01.x, B2); fma2(acc[0][3], A01.x, B3);
            fma2(acc[0][4], A01.x, B4); fma2(acc[0][5], A01.x, B5);
            fma2(acc[0][6], A01.x, B6); fma2(acc[0][7], A01.x, B7);
            fma2(acc[1][0], A01.y, B0); fma2(acc[1][1], A01.y, B1);
            fma2(acc[1][2], A01.y, B2); fma2(acc[1][3], A01.y, B3);
            fma2(acc[1][4], A01.y, B4); fma2(acc[1][5], A01.y, B5);
            fma2(acc[1][6], A01.y, B6); fma2(acc[1][7], A01.y, B7);
        }
        if (kti < NT - 1) cp_wait0();
        __syncthreads();
    }

    float4 bp0 = *(const float4*)(bp + tx * 4);
    float4 bp1 = *(const float4*)(bp + tx * 4 + 64);
    float4 gv0 = *(const float4*)(gamma + tx * 4);
    float4 gv1 = *(const float4*)(gamma + tx * 4 + 64);
    float4 be0 = *(const float4*)(beta + tx * 4);
    float4 be1 = *(const float4*)(beta + tx * 4 + 64);
    const float k1s2 = 0.70710678118654752f;
#pragma unroll
    for (int rp = 0; rp < 2; rp++) {
        float v[2][8];
#pragma unroll
        for (int c = 0; c < 8; c++) upk2(acc[rp][c], v[0][c], v[1][c]);
#pragma unroll
        for (int half = 0; half < 2; half++) {
            int grow = row0 + ty * 4 + rp * 2 + half;
            bool valid = (grow < Nn);
            float4 xv0 = valid ? *(const float4*)(x + grow * Dd + tx * 4)
                               : make_float4(0.f, 0.f, 0.f, 0.f);
            float4 xv1 = valid ? *(const float4*)(x + grow * Dd + tx * 4 + 64)
                               : make_float4(0.f, 0.f, 0.f, 0.f);
            float y[8];
            y[0] = v[half][0] + bp0.x + xv0.x; y[1] = v[half][1] + bp0.y + xv0.y;
            y[2] = v[half][2] + bp0.z + xv0.z; y[3] = v[half][3] + bp0.w + xv0.w;
            y[4] = v[half][4] + bp1.x + xv1.x; y[5] = v[half][5] + bp1.y + xv1.y;
            y[6] = v[half][6] + bp1.z + xv1.z; y[7] = v[half][7] + bp1.w + xv1.w;
            float s = 0.f, ss = 0.f;
#pragma unroll
            for (int j = 0; j < 8; j++) {
                y[j] = 0.5f * y[j] * (1.f + erff(y[j] * k1s2));
                s += y[j]; ss = fmaf(y[j], y[j], ss);
            }
#pragma unroll
            for (int o = 8; o; o >>= 1) {
                s  += __shfl_xor_sync(0xffffffffu, s, o);
                ss += __shfl_xor_sync(0xffffffffu, ss, o);
            }
            float mu = s * (1.f / 128.f);
            float var = ss * (1.f / 128.f) - mu * mu;
            float rstd = rsqrtf(fmaxf(var, 0.f) + 1e-5f);
            if (valid) {
                float4 o0, o1;
                o0.x = (y[0] - mu) * rstd * gv0.x + be0.x;
                o0.y = (y[1] - mu) * rstd * gv0.y + be0.y;
                o0.z = (y[2] - mu) * rstd * gv0.z + be0.z;
                o0.w = (y[3] - mu) * rstd * gv0.w + be0.w;
                o1.x = (y[4] - mu) * rstd * gv1.x + be1.x;
                o1.y = (y[5] - mu) * rstd * gv1.y + be1.y;
                o1.z = (y[6] - mu) * rstd * gv1.z + be1.z;
                o1.w = (y[7] - mu) * rstd * gv1.w + be1.w;
                *(float4*)(out + grow * Dd + tx * 4) = o0;
                *(float4*)(out + grow * Dd + tx * 4 + 64) = o1;
            }
        }
    }
}

// ---------------- launcher (k_gemm1_mma at position 4 for ncu) --------------
extern "C" void kernel_launch(void* const* d_in, const int* in_sizes, int n_in,
                              void* d_out, int out_size) {
    const float* x        = (const float*)d_in[0];
    const int*   ei       = (const int*)d_in[1];   // JAX x64 disabled -> int32
    const float* ea       = (const float*)d_in[2];
    const float* Wl       = (const float*)d_in[3];
    const float* bl       = (const float*)d_in[4];
    const float* Wr       = (const float*)d_in[5];
    const float* br       = (const float*)d_in[6];
    const float* We       = (const float*)d_in[7];
    const float* att      = (const float*)d_in[8];
    const float* bias_out = (const float*)d_in[9];
    const float* Wp       = (const float*)d_in[10];
    const float* bp       = (const float*)d_in[11];
    const float* gamma    = (const float*)d_in[12];
    const float* beta     = (const float*)d_in[13];
    float* out = (float*)d_out;

    cudaFuncSetAttribute(k_gemm1_mma, cudaFuncAttributeMaxDynamicSharedMemorySize, SMEM_G1);

    k_init<<<(Nn + 255) / 256, 256>>>();
    k_cvt_x<<<(Nn * Dd / 2 + 255) / 256, 256>>>(x);
    k_cvt_w<<<dim3(HC / 32, Dd / 32, 2), dim3(32, 8)>>>(Wl, Wr);
    k_gemm1_mma<<<dim3((Nn + 127) / 128, 8), 512, SMEM_G1>>>(bl, br);
    k_degree<<<(EPE + 255) / 256, 256>>>(ei, ea);
    k_scan<<<1, 1024>>>();
    k_scatter<<<(EPE + 255) / 256, 256>>>(ei, ea);
    k_aggregate<<<(Nn * 32 + 255) / 256, 256>>>(We, att, bias_out);
    k_gemm2<<<(Nn + 63) / 64, 256>>>(x, Wp, bp, gamma, beta, out);
}

// round 12
// speedup vs baseline: 1.2259x; 1.2259x over previous
#include <cuda_runtime.h>
#include <cuda_bf16.h>
#include <math.h>
#include <stdint.h>

#define Nn 10000
#define Ee 160000
#define EPE 170000      // E + N self loops
#define Dd 128
#define HC 512
#define ASTRIDE 136     // padded bf16 row stride (272B) -> conflict-free ldmatrix

typedef unsigned long long u64;

// ---------------- cp/smem helpers ----------------
__device__ __forceinline__ uint32_t saddr(const void* p) {
    return (uint32_t)__cvta_generic_to_shared(p);
}

// ---------------- mma.sync helpers ----------------
__device__ __forceinline__ void ldsm4(uint32_t* r, uint32_t addr) {
    asm volatile("ldmatrix.sync.aligned.m8n8.x4.shared.b16 {%0,%1,%2,%3}, [%4];"
        : "=r"(r[0]), "=r"(r[1]), "=r"(r[2]), "=r"(r[3]) : "r"(addr));
}
__device__ __forceinline__ void mma16816(float* c, const uint32_t* a, uint32_t b0, uint32_t b1) {
    asm volatile(
        "mma.sync.aligned.m16n8k16.row.col.f32.bf16.bf16.f32 "
        "{%0,%1,%2,%3}, {%4,%5,%6,%7}, {%8,%9}, {%0,%1,%2,%3};"
        : "+f"(c[0]), "+f"(c[1]), "+f"(c[2]), "+f"(c[3])
        : "r"(a[0]), "r"(a[1]), "r"(a[2]), "r"(a[3]), "r"(b0), "r"(b1));
}

// ---------------- device scratch ----------------
__device__ float g_xl[Nn * HC];
__device__ float g_xr[Nn * HC];
__device__ __nv_bfloat16 g_agghi[Nn * HC];
__device__ __nv_bfloat16 g_agglo[Nn * HC];
__device__ int   g_deg[Nn];
__device__ int   g_off[Nn + 1];
__device__ int   g_cur[Nn];
__device__ int   g_esrc[EPE];
__device__ float g_eav[EPE];
__device__ float g_easum;
__device__ __nv_bfloat16 g_xhi[Nn * Dd];
__device__ __nv_bfloat16 g_xlo[Nn * Dd];
__device__ __nv_bfloat16 g_wthi[2 * HC * Dd];   // [mat][n][k] = W[k][n]
__device__ __nv_bfloat16 g_wtlo[2 * HC * Dd];
__device__ __nv_bfloat16 g_wphi[Dd * HC];       // [n=128][k=512] = Wp[k][n]
__device__ __nv_bfloat16 g_wplo[Dd * HC];

// ---------------- init ----------------
__global__ void k_init() {
    int i = blockIdx.x * blockDim.x + threadIdx.x;
    if (i < Nn) { g_deg[i] = 0; g_cur[i] = 0; }
    if (i == 0) g_easum = 0.f;
}

// ---------------- convert x -> bf16 hi/lo ----------------
__global__ void k_cvt_x(const float* __restrict__ x) {
    int i = blockIdx.x * 256 + threadIdx.x;
    if (i >= Nn * Dd / 2) return;
    float2 v = ((const float2*)x)[i];
    __nv_bfloat16 h0 = __float2bfloat16(v.x), h1 = __float2bfloat16(v.y);
    __nv_bfloat16 l0 = __float2bfloat16(v.x - __bfloat162float(h0));
    __nv_bfloat16 l1 = __float2bfloat16(v.y - __bfloat162float(h1));
    ((__nv_bfloat162*)g_xhi)[i] = __halves2bfloat162(h0, h1);
    ((__nv_bfloat162*)g_xlo)[i] = __halves2bfloat162(l0, l1);
}

// ---------------- transpose+convert Wl/Wr -> [n][k] bf16 hi/lo -------------
__global__ void k_cvt_w(const float* __restrict__ Wl, const float* __restrict__ Wr) {
    __shared__ float t[32][33];
    int m = blockIdx.z;
    const float* W = m ? Wr : Wl;
    int nb = blockIdx.x * 32, kb = blockIdx.y * 32;
    int tx = threadIdx.x, ty = threadIdx.y;
#pragma unroll
    for (int j = 0; j < 4; j++)
        t[ty + 8 * j][tx] = W[(kb + ty + 8 * j) * HC + nb + tx];
    __syncthreads();
#pragma unroll
    for (int j = 0; j < 4; j++) {
        float v = t[tx][ty + 8 * j];
        __nv_bfloat16 h = __float2bfloat16(v);
        __nv_bfloat16 l = __float2bfloat16(v - __bfloat162float(h));
        int o = m * HC * Dd + (nb + ty + 8 * j) * Dd + kb + tx;
        g_wthi[o] = h;
        g_wtlo[o] = l;
    }
}

// ---------------- transpose+convert Wp [512k][128n] -> [n][k] bf16 ---------
__global__ void k_cvt_wp(const float* __restrict__ Wp) {
    __shared__ float t[32][33];
    int nb = blockIdx.x * 32, kb = blockIdx.y * 32;
    int tx = threadIdx.x, ty = threadIdx.y;
#pragma unroll
    for (int j = 0; j < 4; j++)
        t[ty + 8 * j][tx] = Wp[(kb + ty + 8 * j) * Dd + nb + tx];
    __syncthreads();
#pragma unroll
    for (int j = 0; j < 4; j++) {
        float v = t[tx][ty + 8 * j];
        __nv_bfloat16 h = __float2bfloat16(v);
        __nv_bfloat16 l = __float2bfloat16(v - __bfloat162float(h));
        int o = (nb + ty + 8 * j) * HC + kb + tx;
        g_wphi[o] = h;
        g_wplo[o] = l;
    }
}

// ---------------- GEMM1 via mma.sync bf16 (R10-best: 8 warps) --------------
#define SMEM_G1 (4 * 128 * ASTRIDE * 2)   // 139264 B

__global__ __launch_bounds__(256) void k_gemm1_mma(const float* __restrict__ bl,
                                                   const float* __restrict__ br) {
    extern __shared__ __nv_bfloat16 smb[];
    __nv_bfloat16* Ah = smb;
    __nv_bfloat16* Al = Ah + 128 * ASTRIDE;
    __nv_bfloat16* Bh = Al + 128 * ASTRIDE;
    __nv_bfloat16* Bl = Bh + 128 * ASTRIDE;

    int tid = threadIdx.x, wid = tid >> 5, lane = tid & 31;
    int cb = blockIdx.y;
    int mat = cb >> 2, colbase = (cb & 3) * 128;
    const float* bias = mat ? br : bl;
    float* out = mat ? g_xr : g_xl;
    int row0 = blockIdx.x * 128;

    const __nv_bfloat16* gbh = g_wthi + (size_t)mat * HC * Dd + (size_t)colbase * Dd;
    const __nv_bfloat16* gbl = g_wtlo + (size_t)mat * HC * Dd + (size_t)colbase * Dd;

#pragma unroll
    for (int i = 0; i < 8; i++) {
        int idx = tid + i * 256;
        int row = idx >> 4, ch = idx & 15;
        int grow = row0 + row;
        uint4 vh = make_uint4(0, 0, 0, 0), vl = make_uint4(0, 0, 0, 0);
        if (grow < Nn) {
            vh = *(const uint4*)(g_xhi + (size_t)grow * Dd + ch * 8);
            vl = *(const uint4*)(g_xlo + (size_t)grow * Dd + ch * 8);
        }
        *(uint4*)(Ah + row * ASTRIDE + ch * 8) = vh;
        *(uint4*)(Al + row * ASTRIDE + ch * 8) = vl;
        *(uint4*)(Bh + row * ASTRIDE + ch * 8) = *(const uint4*)(gbh + row * Dd + ch * 8);
        *(uint4*)(Bl + row * ASTRIDE + ch * 8) = *(const uint4*)(gbl + row * Dd + ch * 8);
    }
    __syncthreads();

    float acc[4][4][4];
#pragma unroll
    for (int mt = 0; mt < 4; mt++)
#pragma unroll
        for (int nt = 0; nt < 4; nt++)
#pragma unroll
            for (int j = 0; j < 4; j++) acc[mt][nt][j] = 0.f;

    int warpM = wid & 1, warpN = wid >> 1;
    int mbase = warpM * 64, nbase = warpN * 32;
    int t8 = lane >> 3, r8 = lane & 7;
    int aRow = (t8 & 1) * 8 + r8, aK = (t8 >> 1) * 8;
    int bN = (t8 >> 1) * 8 + r8, bK = (t8 & 1) * 8;

#pragma unroll
    for (int term = 0; term < 3; term++) {
        const __nv_bfloat16* Asm = (term == 2) ? Al : Ah;
        const __nv_bfloat16* Bsm = (term == 1) ? Bl : Bh;
#pragma unroll
        for (int ks = 0; ks < 8; ks++) {
            uint32_t a[4][4], b[2][4];
#pragma unroll
            for (int mt = 0; mt < 4; mt++)
                ldsm4(a[mt], saddr(Asm + (mbase + mt * 16 + aRow) * ASTRIDE + ks * 16 + aK));
#pragma unroll
            for (int g = 0; g < 2; g++)
                ldsm4(b[g], saddr(Bsm + (nbase + g * 16 + bN) * ASTRIDE + ks * 16 + bK));
#pragma unroll
            for (int mt = 0; mt < 4; mt++)
#pragma unroll
                for (int nt = 0; nt < 4; nt++)
                    mma16816(acc[mt][nt], a[mt],
                             b[nt >> 1][(nt & 1) * 2], b[nt >> 1][(nt & 1) * 2 + 1]);
        }
    }

    int rA = lane >> 2, cA = 2 * (lane & 3);
#pragma unroll
    for (int nt = 0; nt < 4; nt++) {
        int col = colbase + nbase + nt * 8 + cA;
        float2 bv = *(const float2*)(bias + col);
#pragma unroll
        for (int mt = 0; mt < 4; mt++) {
            int row = row0 + mbase + mt * 16 + rA;
            if (row < Nn) {
                float2 o = make_float2(acc[mt][nt][0] + bv.x, acc[mt][nt][1] + bv.y);
                *(float2*)(out + (size_t)row * HC + col) = o;
            }
            if (row + 8 < Nn) {
                float2 o = make_float2(acc[mt][nt][2] + bv.x, acc[mt][nt][3] + bv.y);
                *(float2*)(out + (size_t)(row + 8) * HC + col) = o;
            }
        }
    }
}

// ---------------- degree histogram + edge_attr sum (fused) ----------------
__global__ void k_degree(const int* __restrict__ ei, const float* __restrict__ ea) {
    __shared__ float sh[8];
    int e = blockIdx.x * blockDim.x + threadIdx.x;
    float v = 0.f;
    if (e < EPE) {
        int dst = (e < Ee) ? ei[Ee + e] : (e - Ee);
        atomicAdd(&g_deg[dst], 1);
        if (e < Ee) v = ea[e];
    }
#pragma unroll
    for (int o = 16; o; o >>= 1) v += __shfl_xor_sync(0xffffffffu, v, o);
    if ((threadIdx.x & 31) == 0) sh[threadIdx.x >> 5] = v;
    __syncthreads();
    if (threadIdx.x == 0) {
        float s = 0.f;
#pragma unroll
        for (int w = 0; w < 8; w++) s += sh[w];
        atomicAdd(&g_easum, s);
    }
}

// ---------------- exclusive scan over N (single block) ----------------
__global__ void k_scan() {
    __shared__ int sb[1024];
    int t = threadIdx.x;
    const int CH = 10;
    int lo = t * CH;
    int s = 0;
    for (int i = 0; i < CH; i++) { int idx = lo + i; if (idx < Nn) s += g_deg[idx]; }
    sb[t] = s;
    __syncthreads();
    for (int o = 1; o < 1024; o <<= 1) {
        int v = (t >= o) ? sb[t - o] : 0;
        __syncthreads();
        sb[t] += v;
        __syncthreads();
    }
    int run = sb[t] - s;
    for (int i = 0; i < CH; i++) {
        int idx = lo + i;
        if (idx < Nn) { g_off[idx] = run; run += g_deg[idx]; }
    }
    if (t == 1023) g_off[Nn] = sb[1023];
}

// ---------------- scatter edges into CSR by dst ----------------
__global__ void k_scatter(const int* __restrict__ ei, const float* __restrict__ ea) {
    int e = blockIdx.x * blockDim.x + threadIdx.x;
    if (e >= EPE) return;
    int src, dst; float a;
    if (e < Ee) { src = ei[e]; dst = ei[Ee + e]; a = ea[e]; }
    else        { src = e - Ee; dst = src; a = g_easum * (1.0f / Ee); }
    int pos = atomicAdd(&g_cur[dst], 1);
    int idx = g_off[dst] + pos;
    g_esrc[idx] = src;
    g_eav[idx]  = a;
}

// ---------------- warp-per-node aggregation (fp32 loads, smem we/at) -------
__global__ __launch_bounds__(256) void k_aggregate(const float* __restrict__ We,
        const float* __restrict__ att, const float* __restrict__ bias_out) {
    __shared__ float s_we[HC], s_at[HC];
    {
        int t = threadIdx.x;
        if (t < 128) ((float4*)s_we)[t] = ((const float4*)We)[t];
        else         ((float4*)s_at)[t - 128] = ((const float4*)att)[t - 128];
    }
    __syncthreads();

    int gw = (blockIdx.x * 256 + threadIdx.x) >> 5;
    if (gw >= Nn) return;
    int lane = threadIdx.x & 31;
    int co = lane * 4;

    float xr[16];
#pragma unroll
    for (int q = 0; q < 4; q++)
        *(float4*)&xr[q*4] = *(const float4*)(g_xr + gw * HC + q * 128 + co);

    float ssum[4] = {0.f, 0.f, 0.f, 0.f};
    float acc[16];
#pragma unroll
    for (int k = 0; k < 16; k++) acc[k] = 0.f;

    int e0 = g_off[gw], e1 = g_off[gw + 1];

    float bufA[16], bufB[16];
    auto ldxv = [&](float* d, int s) {
#pragma unroll
        for (int q = 0; q < 4; q++)
            *(float4*)&d[q*4] = *(const float4*)(g_xl + (size_t)s * HC + q * 128 + co);
    };
    auto process = [&](const float* xv, float a) {
        float p[4];
#pragma unroll
        for (int q = 0; q < 4; q++) {
            float4 we4 = *(const float4*)&s_we[q * 128 + co];
            float4 at4 = *(const float4*)&s_at[q * 128 + co];
            float wej[4] = {we4.x, we4.y, we4.z, we4.w};
            float atj[4] = {at4.x, at4.y, at4.z, at4.w};
            float pq = 0.f;
#pragma unroll
            for (int j = 0; j < 4; j++) {
                float z = xv[q*4+j] + fmaf(a, wej[j], xr[q*4+j]);
                z = fmaxf(z, 0.2f * z);
                pq = fmaf(z, atj[j], pq);
            }
            p[q] = pq;
        }
#pragma unroll
        for (int o = 16; o; o >>= 1) {
            p[0] += __shfl_xor_sync(0xffffffffu, p[0], o);
            p[1] += __shfl_xor_sync(0xffffffffu, p[1], o);
            p[2] += __shfl_xor_sync(0xffffffffu, p[2], o);
            p[3] += __shfl_xor_sync(0xffffffffu, p[3], o);
        }
        float w0 = __expf(p[0]), w1 = __expf(p[1]);
        float w2 = __expf(p[2]), w3 = __expf(p[3]);
        ssum[0] += w0; ssum[1] += w1; ssum[2] += w2; ssum[3] += w3;
#pragma unroll
        for (int j = 0; j < 4; j++) {
            acc[j]    = fmaf(w0, xv[j],    acc[j]);
            acc[4+j]  = fmaf(w1, xv[4+j],  acc[4+j]);
            acc[8+j]  = fmaf(w2, xv[8+j],  acc[8+j]);
            acc[12+j] = fmaf(w3, xv[12+j], acc[12+j]);
        }
    };

    if (e0 < e1) {
        ldxv(bufA, g_esrc[e0]);
        int e = e0;
        for (; e + 2 <= e1; e += 2) {
            ldxv(bufB, g_esrc[e + 1]);
            process(bufA, g_eav[e]);
            if (e + 2 < e1) ldxv(bufA, g_esrc[e + 2]);
            process(bufB, g_eav[e + 1]);
        }
        if (e < e1) process(bufA, g_eav[e]);
    }

    float invq[4];
#pragma unroll
    for (int q = 0; q < 4; q++) invq[q] = 1.f / (ssum[q] + 1e-16f);
#pragma unroll
    for (int q = 0; q < 4; q++) {
        float4 bo = *(const float4*)(bias_out + q * 128 + co);
        float v0 = fmaf(acc[q*4+0], invq[q], bo.x);
        float v1 = fmaf(acc[q*4+1], invq[q], bo.y);
        float v2 = fmaf(acc[q*4+2], invq[q], bo.z);
        float v3 = fmaf(acc[q*4+3], invq[q], bo.w);
        __nv_bfloat16 h0 = __float2bfloat16(v0), h1 = __float2bfloat16(v1);
        __nv_bfloat16 h2 = __float2bfloat16(v2), h3 = __float2bfloat16(v3);
        __nv_bfloat16 l0 = __float2bfloat16(v0 - __bfloat162float(h0));
        __nv_bfloat16 l1 = __float2bfloat16(v1 - __bfloat162float(h1));
        __nv_bfloat16 l2 = __float2bfloat16(v2 - __bfloat162float(h2));
        __nv_bfloat16 l3 = __float2bfloat16(v3 - __bfloat162float(h3));
        size_t o = (size_t)gw * HC + q * 128 + co;
        *(__nv_bfloat162*)(g_agghi + o)     = __halves2bfloat162(h0, h1);
        *(__nv_bfloat162*)(g_agghi + o + 2) = __halves2bfloat162(h2, h3);
        *(__nv_bfloat162*)(g_agglo + o)     = __halves2bfloat162(l0, l1);
        *(__nv_bfloat162*)(g_agglo + o + 2) = __halves2bfloat162(l2, l3);
    }
}

// ---------------- GEMM2 via mma.sync + GELU/LN epilogue ---------------------
// CTA 64 rows x 128 cols, K=512 in 4 single-buffered 128-k stages.
// 8 warps (2M x 4N), warp tile 32x32. C staged through smem for row-LN.
#define SMEM_G2 ((64 * ASTRIDE * 2 + 128 * ASTRIDE * 2) * 2)   // 104448 B

__global__ __launch_bounds__(256) void k_gemm2_mma(const float* __restrict__ x,
        const float* __restrict__ bp, const float* __restrict__ gamma,
        const float* __restrict__ beta, float* __restrict__ out) {
    extern __shared__ __nv_bfloat16 smb2[];
    __nv_bfloat16* Ah = smb2;                       //  64*136
    __nv_bfloat16* Al = Ah + 64 * ASTRIDE;
    __nv_bfloat16* Bh = Al + 64 * ASTRIDE;          // 128*136
    __nv_bfloat16* Bl = Bh + 128 * ASTRIDE;
    float* Csm = (float*)smb2;                      // reused after MMA

    int tid = threadIdx.x, wid = tid >> 5, lane = tid & 31;
    int row0 = blockIdx.x * 64;

    float acc[2][4][4];
#pragma unroll
    for (int mt = 0; mt < 2; mt++)
#pragma unroll
        for (int nt = 0; nt < 4; nt++)
#pragma unroll
            for (int j = 0; j < 4; j++) acc[mt][nt][j] = 0.f;

    int warpM = wid & 1, warpN = wid >> 1;
    int mbase = warpM * 32, nbase = warpN * 32;
    int t8 = lane >> 3, r8 = lane & 7;
    int aRow = (t8 & 1) * 8 + r8, aK = (t8 >> 1) * 8;
    int bN = (t8 >> 1) * 8 + r8, bK = (t8 & 1) * 8;

#pragma unroll 1
    for (int stage = 0; stage < 4; stage++) {
        int k0 = stage * 128;
        // A: 64 rows x 128 k (hi+lo)
#pragma unroll
        for (int i = 0; i < 4; i++) {
            int idx = tid + i * 256;           // 0..1023
            int row = idx >> 4, ch = idx & 15;
            int grow = row0 + row;
            uint4 vh = make_uint4(0, 0, 0, 0), vl = make_uint4(0, 0, 0, 0);
            if (grow < Nn) {
                vh = *(const uint4*)(g_agghi + (size_t)grow * HC + k0 + ch * 8);
                vl = *(const uint4*)(g_agglo + (size_t)grow * HC + k0 + ch * 8);
            }
            *(uint4*)(Ah + row * ASTRIDE + ch * 8) = vh;
            *(uint4*)(Al + row * ASTRIDE + ch * 8) = vl;
        }
        // B: 128 n-rows x 128 k (hi+lo)
#pragma unroll
        for (int i = 0; i < 8; i++) {
            int idx = tid + i * 256;           // 0..2047
            int row = idx >> 4, ch = idx & 15;
            *(uint4*)(Bh + row * ASTRIDE + ch * 8) =
                *(const uint4*)(g_wphi + (size_t)row * HC + k0 + ch * 8);
            *(uint4*)(Bl + row * ASTRIDE + ch * 8) =
                *(const uint4*)(g_wplo + (size_t)row * HC + k0 + ch * 8);
        }
        __syncthreads();

#pragma unroll
        for (int term = 0; term < 3; term++) {
            const __nv_bfloat16* Asm = (term == 2) ? Al : Ah;
            const __nv_bfloat16* Bsm = (term == 1) ? Bl : Bh;
#pragma unroll
            for (int ks = 0; ks < 8; ks++) {
                uint32_t a[2][4], b[2][4];
#pragma unroll
                for (int mt = 0; mt < 2; mt++)
                    ldsm4(a[mt], saddr(Asm + (mbase + mt * 16 + aRow) * ASTRIDE + ks * 16 + aK));
#pragma unroll
                for (int g = 0; g < 2; g++)
                    ldsm4(b[g], saddr(Bsm + (nbase + g * 16 + bN) * ASTRIDE + ks * 16 + bK));
#pragma unroll
                for (int mt = 0; mt < 2; mt++)
#pragma unroll
                    for (int nt = 0; nt < 4; nt++)
                        mma16816(acc[mt][nt], a[mt],
                                 b[nt >> 1][(nt & 1) * 2], b[nt >> 1][(nt & 1) * 2 + 1]);
            }
        }
        __syncthreads();
    }

    // ---- stage C to smem ----
    int rA = lane >> 2, cA = 2 * (lane & 3);
#pragma unroll
    for (int nt = 0; nt < 4; nt++) {
        int col = nbase + nt * 8 + cA;
#pragma unroll
        for (int mt = 0; mt < 2; mt++) {
            int row = mbase + mt * 16 + rA;
            *(float2*)&Csm[row * 128 + col] = make_float2(acc[mt][nt][0], acc[mt][nt][1]);
            *(float2*)&Csm[(row + 8) * 128 + col] = make_float2(acc[mt][nt][2], acc[mt][nt][3]);
        }
    }
    __syncthreads();

    // ---- fused residual + GELU + LayerNorm: warp w owns rows w*8..w*8+7 ----
    int c4 = lane * 4;
    float4 bp4 = *(const float4*)(bp + c4);
    float4 gv4 = *(const float4*)(gamma + c4);
    float4 be4 = *(const float4*)(beta + c4);
    const float k1s2 = 0.70710678118654752f;
#pragma unroll
    for (int r = 0; r < 8; r++) {
        int row = wid * 8 + r;
        int grow = row0 + row;
        bool valid = (grow < Nn);
        float4 v = *(float4*)&Csm[row * 128 + c4];
        float4 xv = valid ? *(const float4*)(x + (size_t)grow * Dd + c4)
                          : make_float4(0.f, 0.f, 0.f, 0.f);
        float y[4];
        y[0] = v.x + bp4.x + xv.x; y[1] = v.y + bp4.y + xv.y;
        y[2] = v.z + bp4.z + xv.z; y[3] = v.w + bp4.w + xv.w;
        float s = 0.f, ss = 0.f;
#pragma unroll
        for (int j = 0; j < 4; j++) {
            y[j] = 0.5f * y[j] * (1.f + erff(y[j] * k1s2));
            s += y[j]; ss = fmaf(y[j], y[j], ss);
        }
#pragma unroll
        for (int o = 16; o; o >>= 1) {
            s  += __shfl_xor_sync(0xffffffffu, s, o);
            ss += __shfl_xor_sync(0xffffffffu, ss, o);
        }
        float mu = s * (1.f / 128.f);
        float var = ss * (1.f / 128.f) - mu * mu;
        float rstd = rsqrtf(fmaxf(var, 0.f) + 1e-5f);
        if (valid) {
            float4 o4;
            o4.x = (y[0] - mu) * rstd * gv4.x + be4.x;
            o4.y = (y[1] - mu) * rstd * gv4.y + be4.y;
            o4.z = (y[2] - mu) * rstd * gv4.z + be4.z;
            o4.w = (y[3] - mu) * rstd * gv4.w + be4.w;
            *(float4*)(out + (size_t)grow * Dd + c4) = o4;
        }
    }
}

// ---------------- launcher (k_gemm1_mma at position 4 for ncu) --------------
extern "C" void kernel_launch(void* const* d_in, const int* in_sizes, int n_in,
                              void* d_out, int out_size) {
    const float* x        = (const float*)d_in[0];
    const int*   ei       = (const int*)d_in[1];   // JAX x64 disabled -> int32
    const float* ea       = (const float*)d_in[2];
    const float* Wl       = (const float*)d_in[3];
    const float* bl       = (const float*)d_in[4];
    const float* Wr       = (const float*)d_in[5];
    const float* br       = (const float*)d_in[6];
    const float* We       = (const float*)d_in[7];
    const float* att      = (const float*)d_in[8];
    const float* bias_out = (const float*)d_in[9];
    const float* Wp       = (const float*)d_in[10];
    const float* bp       = (const float*)d_in[11];
    const float* gamma    = (const float*)d_in[12];
    const float* beta     = (const float*)d_in[13];
    float* out = (float*)d_out;

    cudaFuncSetAttribute(k_gemm1_mma, cudaFuncAttributeMaxDynamicSharedMemorySize, SMEM_G1);
    cudaFuncSetAttribute(k_gemm2_mma, cudaFuncAttributeMaxDynamicSharedMemorySize, SMEM_G2);

    k_cvt_x<<<(Nn * Dd / 2 + 255) / 256, 256>>>(x);
    k_cvt_w<<<dim3(HC / 32, Dd / 32, 2), dim3(32, 8)>>>(Wl, Wr);
    k_init<<<(Nn + 255) / 256, 256>>>();
    k_gemm1_mma<<<dim3((Nn + 127) / 128, 8), 256, SMEM_G1>>>(bl, br);
    k_degree<<<(EPE + 255) / 256, 256>>>(ei, ea);
    k_scan<<<1, 1024>>>();
    k_scatter<<<(EPE + 255) / 256, 256>>>(ei, ea);
    k_cvt_wp<<<dim3(Dd / 32, HC / 32), dim3(32, 8)>>>(Wp);
    k_aggregate<<<(Nn * 32 + 255) / 256, 256>>>(We, att, bias_out);
    k_gemm2_mma<<<(Nn + 63) / 64, 256, SMEM_G2>>>(x, bp, gamma, beta, out);
}

// round 13
// speedup vs baseline: 1.2547x; 1.0235x over previous
#include <cuda_runtime.h>
#include <cuda_bf16.h>
#include <math.h>
#include <stdint.h>

#define Nn 10000
#define Ee 160000
#define EPE 170000      // E + N self loops
#define Dd 128
#define HC 512
#define ASTRIDE 136     // padded bf16 row stride (272B) -> conflict-free ldmatrix

typedef unsigned long long u64;

// ---- channel permutation: storage pos p <-> logical channel c -------------
// c = 128g + 16i + 4q + j   (g=head, i=lane-in-group, q=quad, j=elem)
// p = q*128 + (8g+i)*4 + j  (lane l=8g+i owns its head's channels; loads coalesce)
__device__ __forceinline__ int posOf(int c) {
    int g = c >> 7, r = c & 127, i = r >> 4, o = r & 15, q = o >> 2, j = o & 3;
    return q * 128 + g * 32 + i * 4 + j;
}
__device__ __forceinline__ int chOf(int p) {
    int q = p >> 7, r = p & 127, l = r >> 2, j = r & 3, g = l >> 3, i = l & 7;
    return 128 * g + 16 * i + 4 * q + j;
}

// ---------------- smem helpers ----------------
__device__ __forceinline__ uint32_t saddr(const void* p) {
    return (uint32_t)__cvta_generic_to_shared(p);
}

// ---------------- mma.sync helpers ----------------
__device__ __forceinline__ void ldsm4(uint32_t* r, uint32_t addr) {
    asm volatile("ldmatrix.sync.aligned.m8n8.x4.shared.b16 {%0,%1,%2,%3}, [%4];"
        : "=r"(r[0]), "=r"(r[1]), "=r"(r[2]), "=r"(r[3]) : "r"(addr));
}
__device__ __forceinline__ void mma16816(float* c, const uint32_t* a, uint32_t b0, uint32_t b1) {
    asm volatile(
        "mma.sync.aligned.m16n8k16.row.col.f32.bf16.bf16.f32 "
        "{%0,%1,%2,%3}, {%4,%5,%6,%7}, {%8,%9}, {%0,%1,%2,%3};"
        : "+f"(c[0]), "+f"(c[1]), "+f"(c[2]), "+f"(c[3])
        : "r"(a[0]), "r"(a[1]), "r"(a[2]), "r"(a[3]), "r"(b0), "r"(b1));
}

// ---------------- device scratch ----------------
__device__ float g_xl[Nn * HC];                 // PERMUTED columns
__device__ float g_xr[Nn * HC];                 // PERMUTED columns
__device__ __nv_bfloat16 g_agghi[Nn * HC];      // PERMUTED columns
__device__ __nv_bfloat16 g_agglo[Nn * HC];
__device__ int   g_deg[Nn];
__device__ int   g_off[Nn + 1];
__device__ int   g_cur[Nn];
__device__ int   g_esrc[EPE];
__device__ float g_eav[EPE];
__device__ float g_easum;
__device__ __nv_bfloat16 g_xhi[Nn * Dd];
__device__ __nv_bfloat16 g_xlo[Nn * Dd];
__device__ __nv_bfloat16 g_wthi[2 * HC * Dd];   // [mat][n][k] = W[k][n]
__device__ __nv_bfloat16 g_wtlo[2 * HC * Dd];
__device__ __nv_bfloat16 g_wphi[Dd * HC];       // [n=128][k_perm=512]
__device__ __nv_bfloat16 g_wplo[Dd * HC];

// ---------------- init ----------------
__global__ void k_init() {
    int i = blockIdx.x * blockDim.x + threadIdx.x;
    if (i < Nn) { g_deg[i] = 0; g_cur[i] = 0; }
    if (i == 0) g_easum = 0.f;
}

// ---------------- convert x -> bf16 hi/lo ----------------
__global__ void k_cvt_x(const float* __restrict__ x) {
    int i = blockIdx.x * 256 + threadIdx.x;
    if (i >= Nn * Dd / 2) return;
    float2 v = ((const float2*)x)[i];
    __nv_bfloat16 h0 = __float2bfloat16(v.x), h1 = __float2bfloat16(v.y);
    __nv_bfloat16 l0 = __float2bfloat16(v.x - __bfloat162float(h0));
    __nv_bfloat16 l1 = __float2bfloat16(v.y - __bfloat162float(h1));
    ((__nv_bfloat162*)g_xhi)[i] = __halves2bfloat162(h0, h1);
    ((__nv_bfloat162*)g_xlo)[i] = __halves2bfloat162(l0, l1);
}

// ---------------- transpose+convert Wl/Wr -> [n][k] bf16 hi/lo -------------
__global__ void k_cvt_w(const float* __restrict__ Wl, const float* __restrict__ Wr) {
    __shared__ float t[32][33];
    int m = blockIdx.z;
    const float* W = m ? Wr : Wl;
    int nb = blockIdx.x * 32, kb = blockIdx.y * 32;
    int tx = threadIdx.x, ty = threadIdx.y;
#pragma unroll
    for (int j = 0; j < 4; j++)
        t[ty + 8 * j][tx] = W[(kb + ty + 8 * j) * HC + nb + tx];
    __syncthreads();
#pragma unroll
    for (int j = 0; j < 4; j++) {
        float v = t[tx][ty + 8 * j];
        __nv_bfloat16 h = __float2bfloat16(v);
        __nv_bfloat16 l = __float2bfloat16(v - __bfloat162float(h));
        int o = m * HC * Dd + (nb + ty + 8 * j) * Dd + kb + tx;
        g_wthi[o] = h;
        g_wtlo[o] = l;
    }
}

// ---------------- Wp -> [n][k_perm] bf16 hi/lo (gather permutation) --------
__global__ void k_cvt_wp(const float* __restrict__ Wp) {
    int idx = blockIdx.x * 256 + threadIdx.x;    // 0..65535
    if (idx >= Dd * HC) return;
    int n = idx >> 9, p = idx & 511;
    float v = Wp[(size_t)chOf(p) * Dd + n];
    __nv_bfloat16 h = __float2bfloat16(v);
    __nv_bfloat16 l = __float2bfloat16(v - __bfloat162float(h));
    g_wphi[(size_t)n * HC + p] = h;
    g_wplo[(size_t)n * HC + p] = l;
}

// ---------------- GEMM1 via mma.sync bf16 (8 warps; permuted stores) -------
#define SMEM_G1 (4 * 128 * ASTRIDE * 2)   // 139264 B

__global__ __launch_bounds__(256) void k_gemm1_mma(const float* __restrict__ bl,
                                                   const float* __restrict__ br) {
    extern __shared__ __nv_bfloat16 smb[];
    __nv_bfloat16* Ah = smb;
    __nv_bfloat16* Al = Ah + 128 * ASTRIDE;
    __nv_bfloat16* Bh = Al + 128 * ASTRIDE;
    __nv_bfloat16* Bl = Bh + 128 * ASTRIDE;

    int tid = threadIdx.x, wid = tid >> 5, lane = tid & 31;
    int cb = blockIdx.y;
    int mat = cb >> 2, colbase = (cb & 3) * 128;
    const float* bias = mat ? br : bl;
    float* out = mat ? g_xr : g_xl;
    int row0 = blockIdx.x * 128;

    const __nv_bfloat16* gbh = g_wthi + (size_t)mat * HC * Dd + (size_t)colbase * Dd;
    const __nv_bfloat16* gbl = g_wtlo + (size_t)mat * HC * Dd + (size_t)colbase * Dd;

#pragma unroll
    for (int i = 0; i < 8; i++) {
        int idx = tid + i * 256;
        int row = idx >> 4, ch = idx & 15;
        int grow = row0 + row;
        uint4 vh = make_uint4(0, 0, 0, 0), vl = make_uint4(0, 0, 0, 0);
        if (grow < Nn) {
            vh = *(const uint4*)(g_xhi + (size_t)grow * Dd + ch * 8);
            vl = *(const uint4*)(g_xlo + (size_t)grow * Dd + ch * 8);
        }
        *(uint4*)(Ah + row * ASTRIDE + ch * 8) = vh;
        *(uint4*)(Al + row * ASTRIDE + ch * 8) = vl;
        *(uint4*)(Bh + row * ASTRIDE + ch * 8) = *(const uint4*)(gbh + row * Dd + ch * 8);
        *(uint4*)(Bl + row * ASTRIDE + ch * 8) = *(const uint4*)(gbl + row * Dd + ch * 8);
    }
    __syncthreads();

    float acc[4][4][4];
#pragma unroll
    for (int mt = 0; mt < 4; mt++)
#pragma unroll
        for (int nt = 0; nt < 4; nt++)
#pragma unroll
            for (int j = 0; j < 4; j++) acc[mt][nt][j] = 0.f;

    int warpM = wid & 1, warpN = wid >> 1;
    int mbase = warpM * 64, nbase = warpN * 32;
    int t8 = lane >> 3, r8 = lane & 7;
    int aRow = (t8 & 1) * 8 + r8, aK = (t8 >> 1) * 8;
    int bN = (t8 >> 1) * 8 + r8, bK = (t8 & 1) * 8;

#pragma unroll
    for (int term = 0; term < 3; term++) {
        const __nv_bfloat16* Asm = (term == 2) ? Al : Ah;
        const __nv_bfloat16* Bsm = (term == 1) ? Bl : Bh;
#pragma unroll
        for (int ks = 0; ks < 8; ks++) {
            uint32_t a[4][4], b[2][4];
#pragma unroll
            for (int mt = 0; mt < 4; mt++)
                ldsm4(a[mt], saddr(Asm + (mbase + mt * 16 + aRow) * ASTRIDE + ks * 16 + aK));
#pragma unroll
            for (int g = 0; g < 2; g++)
                ldsm4(b[g], saddr(Bsm + (nbase + g * 16 + bN) * ASTRIDE + ks * 16 + bK));
#pragma unroll
            for (int mt = 0; mt < 4; mt++)
#pragma unroll
                for (int nt = 0; nt < 4; nt++)
                    mma16816(acc[mt][nt], a[mt],
                             b[nt >> 1][(nt & 1) * 2], b[nt >> 1][(nt & 1) * 2 + 1]);
        }
    }

    // permuted epilogue: channel c stored at posOf(c); j-pairs stay adjacent
    int rA = lane >> 2, cA = 2 * (lane & 3);
#pragma unroll
    for (int nt = 0; nt < 4; nt++) {
        int col = colbase + nbase + nt * 8 + cA;
        float2 bv = *(const float2*)(bias + col);
        int p = posOf(col);
#pragma unroll
        for (int mt = 0; mt < 4; mt++) {
            int row = row0 + mbase + mt * 16 + rA;
            if (row < Nn) {
                float2 o = make_float2(acc[mt][nt][0] + bv.x, acc[mt][nt][1] + bv.y);
                *(float2*)(out + (size_t)row * HC + p) = o;
            }
            if (row + 8 < Nn) {
                float2 o = make_float2(acc[mt][nt][2] + bv.x, acc[mt][nt][3] + bv.y);
                *(float2*)(out + (size_t)(row + 8) * HC + p) = o;
            }
        }
    }
}

// ---------------- degree histogram + edge_attr sum (fused) ----------------
__global__ void k_degree(const int* __restrict__ ei, const float* __restrict__ ea) {
    __shared__ float sh[8];
    int e = blockIdx.x * blockDim.x + threadIdx.x;
    float v = 0.f;
    if (e < EPE) {
        int dst = (e < Ee) ? ei[Ee + e] : (e - Ee);
        atomicAdd(&g_deg[dst], 1);
        if (e < Ee) v = ea[e];
    }
#pragma unroll
    for (int o = 16; o; o >>= 1) v += __shfl_xor_sync(0xffffffffu, v, o);
    if ((threadIdx.x & 31) == 0) sh[threadIdx.x >> 5] = v;
    __syncthreads();
    if (threadIdx.x == 0) {
        float s = 0.f;
#pragma unroll
        for (int w = 0; w < 8; w++) s += sh[w];
        atomicAdd(&g_easum, s);
    }
}

// ---------------- exclusive scan over N (single block) ----------------
__global__ void k_scan() {
    __shared__ int sb[1024];
    int t = threadIdx.x;
    const int CH = 10;
    int lo = t * CH;
    int s = 0;
    for (int i = 0; i < CH; i++) { int idx = lo + i; if (idx < Nn) s += g_deg[idx]; }
    sb[t] = s;
    __syncthreads();
    for (int o = 1; o < 1024; o <<= 1) {
        int v = (t >= o) ? sb[t - o] : 0;
        __syncthreads();
        sb[t] += v;
        __syncthreads();
    }
    int run = sb[t] - s;
    for (int i = 0; i < CH; i++) {
        int idx = lo + i;
        if (idx < Nn) { g_off[idx] = run; run += g_deg[idx]; }
    }
    if (t == 1023) g_off[Nn] = sb[1023];
}

// ---------------- scatter edges into CSR by dst ----------------
__global__ void k_scatter(const int* __restrict__ ei, const float* __restrict__ ea) {
    int e = blockIdx.x * blockDim.x + threadIdx.x;
    if (e >= EPE) return;
    int src, dst; float a;
    if (e < Ee) { src = ei[e]; dst = ei[Ee + e]; a = ea[e]; }
    else        { src = e - Ee; dst = src; a = g_easum * (1.0f / Ee); }
    int pos = atomicAdd(&g_cur[dst], 1);
    int idx = g_off[dst] + pos;
    g_esrc[idx] = src;
    g_eav[idx]  = a;
}

// ---------------- warp-per-node aggregation: permuted layout ---------------
// Lane l=8g+i owns head g's channels [16i,16i+16). Loads fully coalesced.
// Per edge: 3 SHFL (group reduce), 1 MUFU. ssum is group-uniform.
__global__ __launch_bounds__(256) void k_aggregate(const float* __restrict__ We,
        const float* __restrict__ att, const float* __restrict__ bias_out) {
    __shared__ float s_we[HC], s_at[HC];
    for (int p = threadIdx.x; p < HC; p += 256) {
        int ch = chOf(p);
        s_we[p] = We[ch];
        s_at[p] = att[ch];
    }
    __syncthreads();

    int gw = (blockIdx.x * 256 + threadIdx.x) >> 5;
    if (gw >= Nn) return;
    int lane = threadIdx.x & 31;
    int co = lane * 4;
    int g = lane >> 3, i = lane & 7;

    float xr[16], we[16], at[16];
#pragma unroll
    for (int q = 0; q < 4; q++) {
        *(float4*)&xr[q*4] = *(const float4*)(g_xr + (size_t)gw * HC + q * 128 + co);
        *(float4*)&we[q*4] = *(const float4*)&s_we[q * 128 + co];
        *(float4*)&at[q*4] = *(const float4*)&s_at[q * 128 + co];
    }

    float ssum = 0.f;
    float acc[16];
#pragma unroll
    for (int k = 0; k < 16; k++) acc[k] = 0.f;

    int e0 = g_off[gw], e1 = g_off[gw + 1];

    float bufA[16], bufB[16];
    auto ldxv = [&](float* d, int s) {
#pragma unroll
        for (int q = 0; q < 4; q++)
            *(float4*)&d[q*4] = *(const float4*)(g_xl + (size_t)s * HC + q * 128 + co);
    };
    auto process = [&](const float* xv, float a) {
        float pa = 0.f, pb = 0.f;
#pragma unroll
        for (int k = 0; k < 8; k++) {
            float z = xv[k] + fmaf(a, we[k], xr[k]);
            z = fmaxf(z, 0.2f * z);
            pa = fmaf(z, at[k], pa);
        }
#pragma unroll
        for (int k = 8; k < 16; k++) {
            float z = xv[k] + fmaf(a, we[k], xr[k]);
            z = fmaxf(z, 0.2f * z);
            pb = fmaf(z, at[k], pb);
        }
        float p = pa + pb;
        p += __shfl_xor_sync(0xffffffffu, p, 1);
        p += __shfl_xor_sync(0xffffffffu, p, 2);
        p += __shfl_xor_sync(0xffffffffu, p, 4);
        float w = __expf(p);
        ssum += w;
#pragma unroll
        for (int k = 0; k < 16; k++) acc[k] = fmaf(w, xv[k], acc[k]);
    };

    if (e0 < e1) {
        ldxv(bufA, g_esrc[e0]);
        int e = e0;
        for (; e + 2 <= e1; e += 2) {
            ldxv(bufB, g_esrc[e + 1]);
            process(bufA, g_eav[e]);
            if (e + 2 < e1) ldxv(bufA, g_esrc[e + 2]);
            process(bufB, g_eav[e + 1]);
        }
        if (e < e1) process(bufA, g_eav[e]);
    }

    float inv = 1.f / (ssum + 1e-16f);
#pragma unroll
    for (int q = 0; q < 4; q++) {
        float4 bo = *(const float4*)(bias_out + g * 128 + i * 16 + q * 4);
        float v0 = fmaf(acc[q*4+0], inv, bo.x);
        float v1 = fmaf(acc[q*4+1], inv, bo.y);
        float v2 = fmaf(acc[q*4+2], inv, bo.z);
        float v3 = fmaf(acc[q*4+3], inv, bo.w);
        __nv_bfloat16 h0 = __float2bfloat16(v0), h1 = __float2bfloat16(v1);
        __nv_bfloat16 h2 = __float2bfloat16(v2), h3 = __float2bfloat16(v3);
        __nv_bfloat16 l0 = __float2bfloat16(v0 - __bfloat162float(h0));
        __nv_bfloat16 l1 = __float2bfloat16(v1 - __bfloat162float(h1));
        __nv_bfloat16 l2 = __float2bfloat16(v2 - __bfloat162float(h2));
        __nv_bfloat16 l3 = __float2bfloat16(v3 - __bfloat162float(h3));
        size_t o = (size_t)gw * HC + q * 128 + co;
        *(__nv_bfloat162*)(g_agghi + o)     = __halves2bfloat162(h0, h1);
        *(__nv_bfloat162*)(g_agghi + o + 2) = __halves2bfloat162(h2, h3);
        *(__nv_bfloat162*)(g_agglo + o)     = __halves2bfloat162(l0, l1);
        *(__nv_bfloat162*)(g_agglo + o + 2) = __halves2bfloat162(l2, l3);
    }
}

// ---------------- GEMM2 via mma.sync + GELU/LN epilogue ---------------------
#define SMEM_G2 ((64 * ASTRIDE * 2 + 128 * ASTRIDE * 2) * 2)   // 104448 B

__global__ __launch_bounds__(256) void k_gemm2_mma(const float* __restrict__ x,
        const float* __restrict__ bp, const float* __restrict__ gamma,
        const float* __restrict__ beta, float* __restrict__ out) {
    extern __shared__ __nv_bfloat16 smb2[];
    __nv_bfloat16* Ah = smb2;
    __nv_bfloat16* Al = Ah + 64 * ASTRIDE;
    __nv_bfloat16* Bh = Al + 64 * ASTRIDE;
    __nv_bfloat16* Bl = Bh + 128 * ASTRIDE;
    float* Csm = (float*)smb2;

    int tid = threadIdx.x, wid = tid >> 5, lane = tid & 31;
    int row0 = blockIdx.x * 64;

    float acc[2][4][4];
#pragma unroll
    for (int mt = 0; mt < 2; mt++)
#pragma unroll
        for (int nt = 0; nt < 4; nt++)
#pragma unroll
            for (int j = 0; j < 4; j++) acc[mt][nt][j] = 0.f;

    int warpM = wid & 1, warpN = wid >> 1;
    int mbase = warpM * 32, nbase = warpN * 32;
    int t8 = lane >> 3, r8 = lane & 7;
    int aRow = (t8 & 1) * 8 + r8, aK = (t8 >> 1) * 8;
    int bN = (t8 >> 1) * 8 + r8, bK = (t8 & 1) * 8;

#pragma unroll 1
    for (int stage = 0; stage < 4; stage++) {
        int k0 = stage * 128;
#pragma unroll
        for (int i = 0; i < 4; i++) {
            int idx = tid + i * 256;
            int row = idx >> 4, ch = idx & 15;
            int grow = row0 + row;
            uint4 vh = make_uint4(0, 0, 0, 0), vl = make_uint4(0, 0, 0, 0);
            if (grow < Nn) {
                vh = *(const uint4*)(g_agghi + (size_t)grow * HC + k0 + ch * 8);
                vl = *(const uint4*)(g_agglo + (size_t)grow * HC + k0 + ch * 8);
            }
            *(uint4*)(Ah + row * ASTRIDE + ch * 8) = vh;
            *(uint4*)(Al + row * ASTRIDE + ch * 8) = vl;
        }
#pragma unroll
        for (int i = 0; i < 8; i++) {
            int idx = tid + i * 256;
            int row = idx >> 4, ch = idx & 15;
            *(uint4*)(Bh + row * ASTRIDE + ch * 8) =
                *(const uint4*)(g_wphi + (size_t)row * HC + k0 + ch * 8);
            *(uint4*)(Bl + row * ASTRIDE + ch * 8) =
                *(const uint4*)(g_wplo + (size_t)row * HC + k0 + ch * 8);
        }
        __syncthreads();

#pragma unroll
        for (int term = 0; term < 3; term++) {
            const __nv_bfloat16* Asm = (term == 2) ? Al : Ah;
            const __nv_bfloat16* Bsm = (term == 1) ? Bl : Bh;
#pragma unroll
            for (int ks = 0; ks < 8; ks++) {
                uint32_t a[2][4], b[2][4];
#pragma unroll
                for (int mt = 0; mt < 2; mt++)
                    ldsm4(a[mt], saddr(Asm + (mbase + mt * 16 + aRow) * ASTRIDE + ks * 16 + aK));
#pragma unroll
                for (int g = 0; g < 2; g++)
                    ldsm4(b[g], saddr(Bsm + (nbase + g * 16 + bN) * ASTRIDE + ks * 16 + bK));
#pragma unroll
                for (int mt = 0; mt < 2; mt++)
#pragma unroll
                    for (int nt = 0; nt < 4; nt++)
                        mma16816(acc[mt][nt], a[mt],
                                 b[nt >> 1][(nt & 1) * 2], b[nt >> 1][(nt & 1) * 2 + 1]);
            }
        }
        __syncthreads();
    }

    int rA = lane >> 2, cA = 2 * (lane & 3);
#pragma unroll
    for (int nt = 0; nt < 4; nt++) {
        int col = nbase + nt * 8 + cA;
#pragma unroll
        for (int mt = 0; mt < 2; mt++) {
            int row = mbase + mt * 16 + rA;
            *(float2*)&Csm[row * 128 + col] = make_float2(acc[mt][nt][0], acc[mt][nt][1]);
            *(float2*)&Csm[(row + 8) * 128 + col] = make_float2(acc[mt][nt][2], acc[mt][nt][3]);
        }
    }
    __syncthreads();

    int c4 = lane * 4;
    float4 bp4 = *(const float4*)(bp + c4);
    float4 gv4 = *(const float4*)(gamma + c4);
    float4 be4 = *(const float4*)(beta + c4);
    const float k1s2 = 0.70710678118654752f;
#pragma unroll
    for (int r = 0; r < 8; r++) {
        int row = wid * 8 + r;
        int grow = row0 + row;
        bool valid = (grow < Nn);
        float4 v = *(float4*)&Csm[row * 128 + c4];
        float4 xv = valid ? *(const float4*)(x + (size_t)grow * Dd + c4)
                          : make_float4(0.f, 0.f, 0.f, 0.f);
        float y[4];
        y[0] = v.x + bp4.x + xv.x; y[1] = v.y + bp4.y + xv.y;
        y[2] = v.z + bp4.z + xv.z; y[3] = v.w + bp4.w + xv.w;
        float s = 0.f, ss = 0.f;
#pragma unroll
        for (int j = 0; j < 4; j++) {
            y[j] = 0.5f * y[j] * (1.f + erff(y[j] * k1s2));
            s += y[j]; ss = fmaf(y[j], y[j], ss);
        }
#pragma unroll
        for (int o = 16; o; o >>= 1) {
            s  += __shfl_xor_sync(0xffffffffu, s, o);
            ss += __shfl_xor_sync(0xffffffffu, ss, o);
        }
        float mu = s * (1.f / 128.f);
        float var = ss * (1.f / 128.f) - mu * mu;
        float rstd = rsqrtf(fmaxf(var, 0.f) + 1e-5f);
        if (valid) {
            float4 o4;
            o4.x = (y[0] - mu) * rstd * gv4.x + be4.x;
            o4.y = (y[1] - mu) * rstd * gv4.y + be4.y;
            o4.z = (y[2] - mu) * rstd * gv4.z + be4.z;
            o4.w = (y[3] - mu) * rstd * gv4.w + be4.w;
            *(float4*)(out + (size_t)grow * Dd + c4) = o4;
        }
    }
}

// ---------------- launcher (k_gemm1_mma at position 4 for ncu) --------------
extern "C" void kernel_launch(void* const* d_in, const int* in_sizes, int n_in,
                              void* d_out, int out_size) {
    const float* x        = (const float*)d_in[0];
    const int*   ei       = (const int*)d_in[1];   // JAX x64 disabled -> int32
    const float* ea       = (const float*)d_in[2];
    const float* Wl       = (const float*)d_in[3];
    const float* bl       = (const float*)d_in[4];
    const float* Wr       = (const float*)d_in[5];
    const float* br       = (const float*)d_in[6];
    const float* We       = (const float*)d_in[7];
    const float* att      = (const float*)d_in[8];
    const float* bias_out = (const float*)d_in[9];
    const float* Wp       = (const float*)d_in[10];
    const float* bp       = (const float*)d_in[11];
    const float* gamma    = (const float*)d_in[12];
    const float* beta     = (const float*)d_in[13];
    float* out = (float*)d_out;

    cudaFuncSetAttribute(k_gemm1_mma, cudaFuncAttributeMaxDynamicSharedMemorySize, SMEM_G1);
    cudaFuncSetAttribute(k_gemm2_mma, cudaFuncAttributeMaxDynamicSharedMemorySize, SMEM_G2);

    k_cvt_x<<<(Nn * Dd / 2 + 255) / 256, 256>>>(x);
    k_cvt_w<<<dim3(HC / 32, Dd / 32, 2), dim3(32, 8)>>>(Wl, Wr);
    k_init<<<(Nn + 255) / 256, 256>>>();
    k_gemm1_mma<<<dim3((Nn + 127) / 128, 8), 256, SMEM_G1>>>(bl, br);
    k_degree<<<(EPE + 255) / 256, 256>>>(ei, ea);
    k_scan<<<1, 1024>>>();
    k_scatter<<<(EPE + 255) / 256, 256>>>(ei, ea);
    k_cvt_wp<<<(Dd * HC + 255) / 256, 256>>>(Wp);
    k_aggregate<<<(Nn * 32 + 255) / 256, 256>>>(We, att, bias_out);
    k_gemm2_mma<<<(Nn + 63) / 64, 256, SMEM_G2>>>(x, bp, gamma, beta, out);
}